// round 11
// baseline (speedup 1.0000x reference)
#include <cuda_runtime.h>
#include <cuda_bf16.h>
#include <cstdint>

#define MDIM 8192
#define KDIM 4096
#define NDIM 4096

#define TILE_M 128
#define TILE_N 256
#define ITERS_PER_TILE 32      // k-positions of 128 per tile
#define NTILES 1024            // 64 m-tiles x 16 n-tiles
#define GRIDX 148
#define THREADS 256
#define NWARPS (THREADS / 32)
#define TOTAL_WARPS (GRIDX * NWARPS)        // 1184
#define UNITS_PER_SLICE 196608              // (8192*16 + 4096*16) 16B units
#define UNITS_PER_WARP 167                  // ceil(196608/1184)

// Tile-major pre-swizzled scratch:
// g_xq: [mt(64)][ks(64)] tiles of 128x64 bf16, rows 128B, XOR-swizzled
// g_wq: [nt(16)][ks(64)] tiles of 256x64 bf16
__device__ __nv_bfloat16 g_xq[(size_t)MDIM * KDIM];
__device__ __nv_bfloat16 g_wq[(size_t)NDIM * KDIM];
__device__ int g_cnt[ITERS_PER_TILE];       // per-k-position completion counters
__device__ int g_epoch;                     // run counter (epoch_kernel)

#define A_TILE_BYTES 16384
#define B_TILE_BYTES 32768
#define A_STEP (2 * A_TILE_BYTES)   // 32768 per position
#define B_STEP (2 * B_TILE_BYTES)   // 65536 per position

// ---------------- helpers ----------------
__device__ __forceinline__ uint32_t smem_u32(const void* p) {
    uint32_t a;
    asm("{ .reg .u64 t; cvta.to.shared.u64 t, %1; cvt.u32.u64 %0, t; }" : "=r"(a) : "l"(p));
    return a;
}
__device__ __forceinline__ void ldm_x4(uint32_t* r, uint32_t addr) {
    asm volatile("ldmatrix.sync.aligned.m8n8.x4.shared.b16 {%0,%1,%2,%3}, [%4];"
                 : "=r"(r[0]), "=r"(r[1]), "=r"(r[2]), "=r"(r[3]) : "r"(addr));
}
__device__ __forceinline__ void mma_bf16(float* d, const uint32_t* a, const uint32_t* b) {
    asm volatile(
        "mma.sync.aligned.m16n8k16.row.col.f32.bf16.bf16.f32 "
        "{%0,%1,%2,%3}, {%4,%5,%6,%7}, {%8,%9}, {%0,%1,%2,%3};"
        : "+f"(d[0]), "+f"(d[1]), "+f"(d[2]), "+f"(d[3])
        : "r"(a[0]), "r"(a[1]), "r"(a[2]), "r"(a[3]), "r"(b[0]), "r"(b[1]));
}
__device__ __forceinline__ uint32_t pack_bf16(float a, float b) {
    __nv_bfloat162 t = __floats2bfloat162_rn(a, b);
    return *reinterpret_cast<uint32_t*>(&t);
}
__device__ __forceinline__ void bulk_ld(uint32_t dst, const void* src, uint32_t bytes,
                                        uint32_t mbar) {
    asm volatile(
        "cp.async.bulk.shared::cta.global.mbarrier::complete_tx::bytes [%0], [%1], %2, [%3];"
        :: "r"(dst), "l"(src), "r"(bytes), "r"(mbar) : "memory");
}
#define MBAR_INIT(addr, cnt) \
    asm volatile("mbarrier.init.shared.b64 [%0], %1;" :: "r"(addr), "r"(cnt) : "memory")
#define MBAR_EXPECT_TX(addr, bytes) \
    asm volatile("mbarrier.arrive.expect_tx.shared.b64 _, [%0], %1;" \
                 :: "r"(addr), "r"(bytes) : "memory")
#define MBAR_ARRIVE(addr) \
    asm volatile("mbarrier.arrive.release.cta.shared.b64 _, [%0];" :: "r"(addr) : "memory")
__device__ __forceinline__ void mbar_wait(uint32_t mbar, uint32_t parity) {
    asm volatile(
        "{\n\t"
        ".reg .pred P;\n\t"
        "WAIT_%=:\n\t"
        "mbarrier.try_wait.parity.acquire.cta.shared::cta.b64 P, [%0], %1, 0x989680;\n\t"
        "@P bra DONE_%=;\n\t"
        "bra WAIT_%=;\n\t"
        "DONE_%=:\n\t"
        "}" :: "r"(mbar), "r"(parity) : "memory");
}
__device__ __forceinline__ void flag_wait(int s, int target) {
    int v;
    do {
        asm volatile("ld.acquire.gpu.global.b32 %0, [%1];"
                     : "=r"(v) : "l"(&g_cnt[s]) : "memory");
    } while (v < target);
}

// epoch bump: one tiny launch per run makes the flag protocol honest per-replay
__global__ void epoch_kernel() { g_epoch += 1; }

// ---------------- inline conversion: one warp-chunk of k-position s ----------------
// position s covers k in [128s, 128(s+1)). Unit = 16B of bf16 output (8 elements).
// A units: id in [0, 131072): m = id>>4, j = id&15. B units: id2 = id-131072.
__device__ __noinline__ void convert_slice(int s, int wg, int lane,
                                           const float* __restrict__ x,
                                           const int* __restrict__ w,
                                           const int* __restrict__ wzp,
                                           float inv, float zp) {
    int base = wg * UNITS_PER_WARP;
#pragma unroll 1
    for (int i = lane; i < UNITS_PER_WARP; i += 32) {
        int id = base + i;
        if (id >= UNITS_PER_SLICE) break;
        if (id < 131072) {
            int m = id >> 4, j = id & 15;
            const float* src = x + (size_t)m * 4096 + (s << 7) + (j << 3);
            float4 v0 = __ldg((const float4*)src);
            float4 v1 = __ldg((const float4*)(src + 4));
            float q[8] = {v0.x, v0.y, v0.z, v0.w, v1.x, v1.y, v1.z, v1.w};
#pragma unroll
            for (int e = 0; e < 8; e++)
                q[e] = fminf(fmaxf(rintf(q[e] * inv) + zp, -128.f), 127.f) - zp;
            uint4 o;
            o.x = pack_bf16(q[0], q[1]); o.y = pack_bf16(q[2], q[3]);
            o.z = pack_bf16(q[4], q[5]); o.w = pack_bf16(q[6], q[7]);
            int mt = m >> 7, row = m & 127, ks = (s << 1) + (j >> 3), u = j & 7;
            size_t dst = (size_t)(mt * 64 + ks) * A_TILE_BYTES + row * 128 +
                         ((u ^ (row & 7)) << 4);
            *reinterpret_cast<uint4*>(reinterpret_cast<char*>(g_xq) + dst) = o;
        } else {
            int id2 = id - 131072;
            int n = id2 >> 4, j = id2 & 15;
            const int* src = w + (size_t)n * 4096 + (s << 7) + (j << 3);
            int4 a = __ldg((const int4*)src);
            int4 c = __ldg((const int4*)(src + 4));
            int zpw = wzp[n];
            uint4 o;
            o.x = pack_bf16((float)(a.x - zpw), (float)(a.y - zpw));
            o.y = pack_bf16((float)(a.z - zpw), (float)(a.w - zpw));
            o.z = pack_bf16((float)(c.x - zpw), (float)(c.y - zpw));
            o.w = pack_bf16((float)(c.z - zpw), (float)(c.w - zpw));
            int nt = n >> 8, row = n & 255, ks = (s << 1) + (j >> 3), u = j & 7;
            size_t dst = (size_t)(nt * 64 + ks) * B_TILE_BYTES + row * 128 +
                         ((u ^ (row & 7)) << 4);
            *reinterpret_cast<uint4*>(reinterpret_cast<char*>(g_wq) + dst) = o;
        }
    }
    __syncwarp();
    __threadfence();                       // release: make stores GPU-visible
    if (lane == 0) atomicAdd(&g_cnt[s], 1);
}

// ---------------- persistent HMMA bf16 GEMM + fused conversion ----------------
// smem: [0,16) full mbars, [16,32) empty mbars, stages @4096 (96KB each)
#define S_STAGE (A_STEP + B_STEP)               // 98304
#define S_BUF 4096
#define SMEM_BYTES (S_BUF + 2 * S_STAGE)        // 200704

__device__ __forceinline__ void tile_coords(int t, int& mt, int& nt) {
    int g = t >> 7;          // group of 8 m-tiles x 16 n-tiles
    int r = t & 127;
    mt = g * 8 + (r & 7);
    nt = r >> 3;
}

__global__ void __launch_bounds__(THREADS, 1)
gemm_kernel(const float* __restrict__ x, const int* __restrict__ w,
            const float* __restrict__ wscale, const float* __restrict__ in_scale,
            const int* __restrict__ izp_p, const int* __restrict__ wzp,
            const int* __restrict__ bias_int, const float* __restrict__ bias_scale,
            float* __restrict__ out) {
    extern __shared__ __align__(1024) char smem[];
    const uint32_t sbase = smem_u32(smem);
    const int tid = threadIdx.x;
    const int lane = tid & 31;
    const int wid = tid >> 5;
    const int warpM = wid >> 2;       // 2 -> 64 rows each
    const int warpN = wid & 3;        // 4 -> 64 cols each
    const int bid = blockIdx.x;
    const int wg = bid * NWARPS + wid;          // global warp id, 0..1183

    const uint32_t FULL0 = sbase, FULL1 = sbase + 8;
    const uint32_t EMPTY0 = sbase + 16, EMPTY1 = sbase + 24;

    const char* xbase = reinterpret_cast<const char*>(g_xq);
    const char* wbase = reinterpret_cast<const char*>(g_wq);

    const int epoch = *(volatile int*)&g_epoch;     // epoch_kernel ran before us
    const int target = epoch * TOTAL_WARPS;
    const float is = in_scale[0];
    const float inv = 1.0f / is;
    const float zp = (float)izp_p[0];

    if (tid == 0) {
        MBAR_INIT(FULL0, 1);
        MBAR_INIT(FULL1, 1);
        MBAR_INIT(EMPTY0, NWARPS);
        MBAR_INIT(EMPTY1, NWARPS);
    }
    __syncthreads();

    // pre-loop: convert k-positions 0..2 (lag-3 pipeline seed)
#pragma unroll 1
    for (int s = 0; s < 3; s++)
        convert_slice(s, wg, lane, x, w, wzp, inv, zp);

    int t = bid;
    int mt, nt;
    tile_coords(t, mt, nt);

    // prologue: position 0 in flight once globally converted
    if (tid == 0) {
        flag_wait(0, target);
        MBAR_EXPECT_TX(FULL0, S_STAGE);
        bulk_ld(sbase + S_BUF, xbase + (size_t)mt * 64 * A_TILE_BYTES, A_STEP, FULL0);
        bulk_ld(sbase + S_BUF + A_STEP, wbase + (size_t)nt * 64 * B_TILE_BYTES,
                B_STEP, FULL0);
    }

    float acc[4][8][4];
#pragma unroll
    for (int i = 0; i < 4; i++)
#pragma unroll
        for (int j = 0; j < 8; j++)
#pragma unroll
            for (int q = 0; q < 4; q++) acc[i][j][q] = 0.0f;

    // ldmatrix lane-address components (swizzled rows of 128B)
    const int a_row = lane & 15;
    const int a_kh = (lane >> 4) & 1;
    const int b_noff = (lane & 7) + ((lane & 16) >> 1);
    const int b_kh = (lane >> 3) & 1;

    int rA[4], rB[4];
#pragma unroll
    for (int mi = 0; mi < 4; mi++) rA[mi] = warpM * 64 + mi * 16 + a_row;
#pragma unroll
    for (int np = 0; np < 4; np++) rB[np] = warpN * 64 + np * 16 + b_noff;

    uint32_t git = 0;   // flat position counter (pipeline phase source)

    while (true) {
#pragma unroll 1
        for (int it = 0; it < ITERS_PER_TILE; it++, git++) {
            // fused prelude: convert position git+3 (first tile only; lag 3)
            int cs = (int)git + 3;
            if (cs < ITERS_PER_TILE)
                convert_slice(cs, wg, lane, x, w, wzp, inv, zp);

            // producer: issue load for flat position git+1
            if (tid == 0) {
                int nit = it + 1;
                int t2 = t;
                if (nit == ITERS_PER_TILE) { nit = 0; t2 = t + GRIDX; }
                if (t2 < NTILES) {
                    int mt2, nt2;
                    tile_coords(t2, mt2, nt2);
                    uint32_t pgit = git + 1;
                    uint32_t s = pgit & 1;
                    uint32_t j = pgit >> 1;
                    if (j > 0) mbar_wait(s ? EMPTY1 : EMPTY0, (j - 1) & 1);
                    if (pgit < ITERS_PER_TILE) flag_wait((int)pgit, target);
                    uint32_t fmb = s ? FULL1 : FULL0;
                    MBAR_EXPECT_TX(fmb, S_STAGE);
                    uint32_t dst = sbase + S_BUF + s * S_STAGE;
                    bulk_ld(dst, xbase + (size_t)(mt2 * 64 + nit * 2) * A_TILE_BYTES,
                            A_STEP, fmb);
                    bulk_ld(dst + A_STEP,
                            wbase + (size_t)(nt2 * 64 + nit * 2) * B_TILE_BYTES,
                            B_STEP, fmb);
                }
            }

            uint32_t slot = git & 1;
            mbar_wait(slot ? FULL1 : FULL0, (git >> 1) & 1);

            uint32_t sA = sbase + S_BUF + slot * S_STAGE;
            uint32_t sB = sA + A_STEP;

#pragma unroll
            for (int ks = 0; ks < 8; ks++) {   // eight k=16 steps
                uint32_t a[4][4], b[4][4];
                uint32_t sAsub = sA + (ks >> 2) * A_TILE_BYTES;
                uint32_t sBsub = sB + (ks >> 2) * B_TILE_BYTES;
                int uA = (ks & 3) * 2 + a_kh;
                int uB = (ks & 3) * 2 + b_kh;
#pragma unroll
                for (int mi = 0; mi < 4; mi++)
                    ldm_x4(a[mi], sAsub + rA[mi] * 128 + ((uA ^ (rA[mi] & 7)) << 4));
#pragma unroll
                for (int np = 0; np < 4; np++)
                    ldm_x4(b[np], sBsub + rB[np] * 128 + ((uB ^ (rB[np] & 7)) << 4));
#pragma unroll
                for (int mi = 0; mi < 4; mi++)
#pragma unroll
                    for (int ni = 0; ni < 8; ni++)
                        mma_bf16(acc[mi][ni], a[mi], &b[ni >> 1][(ni & 1) * 2]);
            }

            if (lane == 0) MBAR_ARRIVE(slot ? EMPTY1 : EMPTY0);
        }

        // epilogue for tile t (next tile's stage-0 load already in flight)
        {
            const int m0 = mt * TILE_M;
            const int n0 = nt * TILE_N;
            const int gid = lane >> 2, tig = lane & 3;
#pragma unroll
            for (int ni = 0; ni < 8; ni++) {
                int n = n0 + warpN * 64 + ni * 8 + tig * 2;
                float al0 = is * wscale[n];
                float al1 = is * wscale[n + 1];
                float be0 = (float)bias_int[n] * bias_scale[n];
                float be1 = (float)bias_int[n + 1] * bias_scale[n + 1];
#pragma unroll
                for (int mi = 0; mi < 4; mi++) {
                    size_t r = (size_t)m0 + warpM * 64 + mi * 16 + gid;
                    float2 v0 = {acc[mi][ni][0] * al0 + be0, acc[mi][ni][1] * al1 + be1};
                    float2 v1 = {acc[mi][ni][2] * al0 + be0, acc[mi][ni][3] * al1 + be1};
                    *reinterpret_cast<float2*>(out + r * NDIM + n) = v0;
                    *reinterpret_cast<float2*>(out + (r + 8) * NDIM + n) = v1;
                    acc[mi][ni][0] = 0.0f; acc[mi][ni][1] = 0.0f;
                    acc[mi][ni][2] = 0.0f; acc[mi][ni][3] = 0.0f;
                }
            }
        }

        t += GRIDX;
        if (t >= NTILES) break;
        tile_coords(t, mt, nt);
    }
}

// ---------------- launch ----------------
extern "C" void kernel_launch(void* const* d_in, const int* in_sizes, int n_in,
                              void* d_out, int out_size) {
    const float* x = (const float*)d_in[0];
    const int* w = (const int*)d_in[1];
    const float* wsc = (const float*)d_in[2];
    const int* wzp = (const int*)d_in[3];
    const float* isc = (const float*)d_in[4];
    const int* izp = (const int*)d_in[5];
    const int* bi = (const int*)d_in[6];
    const float* bsc = (const float*)d_in[7];
    float* out = (float*)d_out;

    cudaFuncSetAttribute(gemm_kernel, cudaFuncAttributeMaxDynamicSharedMemorySize,
                         SMEM_BYTES);

    epoch_kernel<<<1, 1>>>();
    gemm_kernel<<<GRIDX, THREADS, SMEM_BYTES>>>(x, w, wsc, isc, izp, wzp, bi, bsc, out);
}

// round 12
// speedup vs baseline: 1.0929x; 1.0929x over previous
#include <cuda_runtime.h>
#include <cuda_bf16.h>
#include <cstdint>

#define MDIM 8192
#define KDIM 4096
#define NDIM 4096

#define TILE_M 128
#define TILE_N 128
#define ITERS_PER_TILE 64      // K=64 steps per tile
#define NTILES 2048            // 64 m-tiles x 32 n-tiles
#define GRIDX 296              // 2 CTAs per SM
#define THREADS 128
#define NWARPS (THREADS / 32)
#define NSLOTS 3

// Tile-major pre-swizzled scratch:
// g_xq: [mt(64)][ks(64)] tiles of 128x64 bf16, rows 128B, XOR-swizzled
// g_wq: [nt256(16)][ks(64)] tiles of 256x64 bf16 (rows 0-127 = first 16KB half)
__device__ __nv_bfloat16 g_xq[(size_t)MDIM * KDIM];
__device__ __nv_bfloat16 g_wq[(size_t)NDIM * KDIM];

#define A_TILE_BYTES 16384
#define B_TILE_BYTES 32768
#define AB_HALF 16384          // 128 rows x 128B

// ---------------- helpers ----------------
__device__ __forceinline__ uint32_t smem_u32(const void* p) {
    uint32_t a;
    asm("{ .reg .u64 t; cvta.to.shared.u64 t, %1; cvt.u32.u64 %0, t; }" : "=r"(a) : "l"(p));
    return a;
}
__device__ __forceinline__ void ldm_x4(uint32_t* r, uint32_t addr) {
    asm volatile("ldmatrix.sync.aligned.m8n8.x4.shared.b16 {%0,%1,%2,%3}, [%4];"
                 : "=r"(r[0]), "=r"(r[1]), "=r"(r[2]), "=r"(r[3]) : "r"(addr));
}
__device__ __forceinline__ void mma_bf16(float* d, const uint32_t* a, const uint32_t* b) {
    asm volatile(
        "mma.sync.aligned.m16n8k16.row.col.f32.bf16.bf16.f32 "
        "{%0,%1,%2,%3}, {%4,%5,%6,%7}, {%8,%9}, {%0,%1,%2,%3};"
        : "+f"(d[0]), "+f"(d[1]), "+f"(d[2]), "+f"(d[3])
        : "r"(a[0]), "r"(a[1]), "r"(a[2]), "r"(a[3]), "r"(b[0]), "r"(b[1]));
}
__device__ __forceinline__ uint32_t pack_bf16(float a, float b) {
    __nv_bfloat162 t = __floats2bfloat162_rn(a, b);
    return *reinterpret_cast<uint32_t*>(&t);
}
__device__ __forceinline__ void bulk_ld(uint32_t dst, const void* src, uint32_t bytes,
                                        uint32_t mbar) {
    asm volatile(
        "cp.async.bulk.shared::cta.global.mbarrier::complete_tx::bytes [%0], [%1], %2, [%3];"
        :: "r"(dst), "l"(src), "r"(bytes), "r"(mbar) : "memory");
}
#define MBAR_INIT(addr, cnt) \
    asm volatile("mbarrier.init.shared.b64 [%0], %1;" :: "r"(addr), "r"(cnt) : "memory")
#define MBAR_EXPECT_TX(addr, bytes) \
    asm volatile("mbarrier.arrive.expect_tx.shared.b64 _, [%0], %1;" \
                 :: "r"(addr), "r"(bytes) : "memory")
#define MBAR_ARRIVE(addr) \
    asm volatile("mbarrier.arrive.release.cta.shared.b64 _, [%0];" :: "r"(addr) : "memory")
__device__ __forceinline__ void mbar_wait(uint32_t mbar, uint32_t parity) {
    asm volatile(
        "{\n\t"
        ".reg .pred P;\n\t"
        "WAIT_%=:\n\t"
        "mbarrier.try_wait.parity.acquire.cta.shared::cta.b64 P, [%0], %1, 0x989680;\n\t"
        "@P bra DONE_%=;\n\t"
        "bra WAIT_%=;\n\t"
        "DONE_%=:\n\t"
        "}" :: "r"(mbar), "r"(parity) : "memory");
}

// ---------------- fused prelude: quantize x + convert w, tile-major swizzled ------
__global__ void __launch_bounds__(256) prelude_kernel(const float* __restrict__ x,
                                                      const int* __restrict__ w,
                                                      const float* __restrict__ is_p,
                                                      const int* __restrict__ izp_p,
                                                      const int* __restrict__ wzp) {
    int b = blockIdx.x;
    if (b < 16384) {
        size_t base = ((size_t)b * 256 + threadIdx.x) * 8;
        float inv = 1.0f / is_p[0];
        float zp = (float)izp_p[0];
        float4 v0 = *(const float4*)(x + base);
        float4 v1 = *(const float4*)(x + base + 4);
        float q[8];
        q[0] = v0.x; q[1] = v0.y; q[2] = v0.z; q[3] = v0.w;
        q[4] = v1.x; q[5] = v1.y; q[6] = v1.z; q[7] = v1.w;
#pragma unroll
        for (int i = 0; i < 8; i++)
            q[i] = fminf(fmaxf(rintf(q[i] * inv) + zp, -128.f), 127.f) - zp;
        uint4 o;
        o.x = pack_bf16(q[0], q[1]);
        o.y = pack_bf16(q[2], q[3]);
        o.z = pack_bf16(q[4], q[5]);
        o.w = pack_bf16(q[6], q[7]);
        int m = (int)(base >> 12);
        int k = (int)(base & 4095);
        int mt = m >> 7, row = m & 127;
        int ks = k >> 6, u = (k & 63) >> 3;
        size_t dst = (size_t)(mt * 64 + ks) * A_TILE_BYTES +
                     row * 128 + ((u ^ (row & 7)) << 4);
        *reinterpret_cast<uint4*>(reinterpret_cast<char*>(g_xq) + dst) = o;
    } else {
        size_t base = ((size_t)(b - 16384) * 256 + threadIdx.x) * 8;
        int n = (int)(base >> 12);
        int k = (int)(base & 4095);
        int zp = wzp[n];
        int4 a = *(const int4*)(w + base);
        int4 c = *(const int4*)(w + base + 4);
        uint4 o;
        o.x = pack_bf16((float)(a.x - zp), (float)(a.y - zp));
        o.y = pack_bf16((float)(a.z - zp), (float)(a.w - zp));
        o.z = pack_bf16((float)(c.x - zp), (float)(c.y - zp));
        o.w = pack_bf16((float)(c.z - zp), (float)(c.w - zp));
        int nt = n >> 8, row = n & 255;
        int ks = k >> 6, u = (k & 63) >> 3;
        size_t dst = (size_t)(nt * 64 + ks) * B_TILE_BYTES +
                     row * 128 + ((u ^ (row & 7)) << 4);
        *reinterpret_cast<uint4*>(reinterpret_cast<char*>(g_wq) + dst) = o;
    }
}

// ---------------- persistent HMMA bf16 GEMM: 128x128 tiles, 2 CTAs/SM ----------------
// smem: [0,24) full mbars(3), [24,48) empty mbars(3), stages @4096 (32KB each)
#define S_STAGE (2 * AB_HALF)                   // 32768: A 16KB + B 16KB
#define S_BUF 4096
#define SMEM_BYTES (S_BUF + NSLOTS * S_STAGE)   // 102400

__device__ __forceinline__ void tile_coords(int t, int& mt, int& nt) {
    int g = t >> 8;          // group of 8 m-tiles x 32 n-tiles
    int r = t & 255;
    mt = g * 8 + (r & 7);
    nt = r >> 3;             // 0..31
}

__global__ void __launch_bounds__(THREADS, 2)
gemm_kernel(const float* __restrict__ wscale, const float* __restrict__ in_scale,
            const int* __restrict__ bias_int, const float* __restrict__ bias_scale,
            float* __restrict__ out) {
    extern __shared__ __align__(1024) char smem[];
    const uint32_t sbase = smem_u32(smem);
    const int tid = threadIdx.x;
    const int lane = tid & 31;
    const int wid = tid >> 5;
    const int warpM = wid >> 1;       // 2 -> 64 rows each
    const int warpN = wid & 1;        // 2 -> 64 cols each
    const int bid = blockIdx.x;

    const char* xbase = reinterpret_cast<const char*>(g_xq);
    const char* wbase = reinterpret_cast<const char*>(g_wq);

    if (tid == 0) {
#pragma unroll
        for (int s = 0; s < NSLOTS; s++) {
            MBAR_INIT(sbase + s * 8, 1);
            MBAR_INIT(sbase + 24 + s * 8, NWARPS);
        }
    }
    __syncthreads();

    const float is = in_scale[0];

    int t = bid;
    int mt, nt;
    tile_coords(t, mt, nt);

    // prologue: positions 0,1 in flight (slots 0,1)
    if (tid == 0) {
#pragma unroll
        for (int p = 0; p < 2; p++) {
            uint32_t fmb = sbase + p * 8;
            uint32_t dst = sbase + S_BUF + p * S_STAGE;
            MBAR_EXPECT_TX(fmb, S_STAGE);
            bulk_ld(dst, xbase + (size_t)(mt * 64 + p) * A_TILE_BYTES, AB_HALF, fmb);
            bulk_ld(dst + AB_HALF,
                    wbase + (size_t)((nt >> 1) * 64 + p) * B_TILE_BYTES +
                            (size_t)(nt & 1) * AB_HALF,
                    AB_HALF, fmb);
        }
    }

    float acc[4][8][4];
#pragma unroll
    for (int i = 0; i < 4; i++)
#pragma unroll
        for (int j = 0; j < 8; j++)
#pragma unroll
            for (int q = 0; q < 4; q++) acc[i][j][q] = 0.0f;

    // ldmatrix lane-address components (swizzled rows of 128B)
    const int a_row = lane & 15;
    const int a_kh = (lane >> 4) & 1;
    const int b_noff = (lane & 7) + ((lane & 16) >> 1);
    const int b_kh = (lane >> 3) & 1;

    int rA[4], rB[4];
#pragma unroll
    for (int mi = 0; mi < 4; mi++) rA[mi] = warpM * 64 + mi * 16 + a_row;
#pragma unroll
    for (int np = 0; np < 4; np++) rB[np] = warpN * 64 + np * 16 + b_noff;

    uint32_t git = 0;   // flat K64-position counter

    while (true) {
#pragma unroll 1
        for (int it = 0; it < ITERS_PER_TILE; it++, git++) {
            // producer: issue load for flat position git+2
            if (tid == 0) {
                uint32_t pgit = git + 2;
                int pt = bid + GRIDX * (int)(pgit >> 6);
                if (pt < NTILES) {
                    int pit = (int)(pgit & 63);
                    int pmt, pnt;
                    tile_coords(pt, pmt, pnt);
                    uint32_t s = pgit % NSLOTS;
                    uint32_t j = pgit / NSLOTS;
                    if (j > 0) mbar_wait(sbase + 24 + s * 8, (j - 1) & 1);
                    uint32_t fmb = sbase + s * 8;
                    MBAR_EXPECT_TX(fmb, S_STAGE);
                    uint32_t dst = sbase + S_BUF + s * S_STAGE;
                    bulk_ld(dst, xbase + (size_t)(pmt * 64 + pit) * A_TILE_BYTES,
                            AB_HALF, fmb);
                    bulk_ld(dst + AB_HALF,
                            wbase + (size_t)((pnt >> 1) * 64 + pit) * B_TILE_BYTES +
                                    (size_t)(pnt & 1) * AB_HALF,
                            AB_HALF, fmb);
                }
            }

            uint32_t slot = git % NSLOTS;
            mbar_wait(sbase + slot * 8, (git / NSLOTS) & 1);

            uint32_t sA = sbase + S_BUF + slot * S_STAGE;
            uint32_t sB = sA + AB_HALF;

#pragma unroll
            for (int ks = 0; ks < 4; ks++) {   // four k=16 steps
                uint32_t a[4][4], b[4][4];
                int uA = ks * 2 + a_kh;
                int uB = ks * 2 + b_kh;
#pragma unroll
                for (int mi = 0; mi < 4; mi++)
                    ldm_x4(a[mi], sA + rA[mi] * 128 + ((uA ^ (rA[mi] & 7)) << 4));
#pragma unroll
                for (int np = 0; np < 4; np++)
                    ldm_x4(b[np], sB + rB[np] * 128 + ((uB ^ (rB[np] & 7)) << 4));
#pragma unroll
                for (int mi = 0; mi < 4; mi++)
#pragma unroll
                    for (int ni = 0; ni < 8; ni++)
                        mma_bf16(acc[mi][ni], a[mi], &b[ni >> 1][(ni & 1) * 2]);
            }

            if (lane == 0) MBAR_ARRIVE(sbase + 24 + slot * 8);
        }

        // epilogue for tile t (next tile's loads already in flight)
        {
            const int m0 = mt * TILE_M;
            const int n0 = nt * TILE_N;
            const int gid = lane >> 2, tig = lane & 3;
#pragma unroll
            for (int ni = 0; ni < 8; ni++) {
                int n = n0 + warpN * 64 + ni * 8 + tig * 2;
                float al0 = is * wscale[n];
                float al1 = is * wscale[n + 1];
                float be0 = (float)bias_int[n] * bias_scale[n];
                float be1 = (float)bias_int[n + 1] * bias_scale[n + 1];
#pragma unroll
                for (int mi = 0; mi < 4; mi++) {
                    size_t r = (size_t)m0 + warpM * 64 + mi * 16 + gid;
                    float2 v0 = {acc[mi][ni][0] * al0 + be0, acc[mi][ni][1] * al1 + be1};
                    float2 v1 = {acc[mi][ni][2] * al0 + be0, acc[mi][ni][3] * al1 + be1};
                    *reinterpret_cast<float2*>(out + r * NDIM + n) = v0;
                    *reinterpret_cast<float2*>(out + (r + 8) * NDIM + n) = v1;
                    acc[mi][ni][0] = 0.0f; acc[mi][ni][1] = 0.0f;
                    acc[mi][ni][2] = 0.0f; acc[mi][ni][3] = 0.0f;
                }
            }
        }

        t += GRIDX;
        if (t >= NTILES) break;
        tile_coords(t, mt, nt);
    }
}

// ---------------- launch ----------------
extern "C" void kernel_launch(void* const* d_in, const int* in_sizes, int n_in,
                              void* d_out, int out_size) {
    const float* x = (const float*)d_in[0];
    const int* w = (const int*)d_in[1];
    const float* wsc = (const float*)d_in[2];
    const int* wzp = (const int*)d_in[3];
    const float* isc = (const float*)d_in[4];
    const int* izp = (const int*)d_in[5];
    const int* bi = (const int*)d_in[6];
    const float* bsc = (const float*)d_in[7];
    float* out = (float*)d_out;

    cudaFuncSetAttribute(gemm_kernel, cudaFuncAttributeMaxDynamicSharedMemorySize,
                         SMEM_BYTES);

    prelude_kernel<<<16384 + 8192, 256>>>(x, w, isc, izp, wzp);
    gemm_kernel<<<GRIDX, THREADS, SMEM_BYTES>>>(wsc, isc, bi, bsc, out);
}

// round 13
// speedup vs baseline: 1.1010x; 1.0074x over previous
#include <cuda_runtime.h>
#include <cuda_bf16.h>
#include <cstdint>

#define MDIM 8192
#define KDIM 4096
#define NDIM 4096

#define TILE_M 128
#define TILE_N 256
#define ITERS_PER_TILE 32      // k-positions of 128 per tile
#define NTILES 1024            // 64 m-tiles x 16 n-tiles
#define GRIDX 148
#define THREADS 288            // 8 compute warps + 1 producer warp
#define NCOMPUTE_WARPS 8

// Tile-major pre-swizzled scratch:
// g_xq: [mt(64)][ks(64)] tiles of 128x64 bf16, rows 128B, XOR-swizzled
// g_wq: [nt(16)][ks(64)] tiles of 256x64 bf16
__device__ __nv_bfloat16 g_xq[(size_t)MDIM * KDIM];
__device__ __nv_bfloat16 g_wq[(size_t)NDIM * KDIM];

#define A_TILE_BYTES 16384
#define B_TILE_BYTES 32768
#define A_STEP (2 * A_TILE_BYTES)   // 32768 per position
#define B_STEP (2 * B_TILE_BYTES)   // 65536 per position

// ---------------- helpers ----------------
__device__ __forceinline__ uint32_t smem_u32(const void* p) {
    uint32_t a;
    asm("{ .reg .u64 t; cvta.to.shared.u64 t, %1; cvt.u32.u64 %0, t; }" : "=r"(a) : "l"(p));
    return a;
}
__device__ __forceinline__ void ldm_x4(uint32_t* r, uint32_t addr) {
    asm volatile("ldmatrix.sync.aligned.m8n8.x4.shared.b16 {%0,%1,%2,%3}, [%4];"
                 : "=r"(r[0]), "=r"(r[1]), "=r"(r[2]), "=r"(r[3]) : "r"(addr));
}
__device__ __forceinline__ void mma_bf16(float* d, const uint32_t* a, const uint32_t* b) {
    asm volatile(
        "mma.sync.aligned.m16n8k16.row.col.f32.bf16.bf16.f32 "
        "{%0,%1,%2,%3}, {%4,%5,%6,%7}, {%8,%9}, {%0,%1,%2,%3};"
        : "+f"(d[0]), "+f"(d[1]), "+f"(d[2]), "+f"(d[3])
        : "r"(a[0]), "r"(a[1]), "r"(a[2]), "r"(a[3]), "r"(b[0]), "r"(b[1]));
}
__device__ __forceinline__ uint32_t pack_bf16(float a, float b) {
    __nv_bfloat162 t = __floats2bfloat162_rn(a, b);
    return *reinterpret_cast<uint32_t*>(&t);
}
__device__ __forceinline__ void bulk_ld(uint32_t dst, const void* src, uint32_t bytes,
                                        uint32_t mbar) {
    asm volatile(
        "cp.async.bulk.shared::cta.global.mbarrier::complete_tx::bytes [%0], [%1], %2, [%3];"
        :: "r"(dst), "l"(src), "r"(bytes), "r"(mbar) : "memory");
}
#define MBAR_INIT(addr, cnt) \
    asm volatile("mbarrier.init.shared.b64 [%0], %1;" :: "r"(addr), "r"(cnt) : "memory")
#define MBAR_EXPECT_TX(addr, bytes) \
    asm volatile("mbarrier.arrive.expect_tx.shared.b64 _, [%0], %1;" \
                 :: "r"(addr), "r"(bytes) : "memory")
#define MBAR_ARRIVE(addr) \
    asm volatile("mbarrier.arrive.release.cta.shared.b64 _, [%0];" :: "r"(addr) : "memory")
__device__ __forceinline__ void mbar_wait(uint32_t mbar, uint32_t parity) {
    asm volatile(
        "{\n\t"
        ".reg .pred P;\n\t"
        "WAIT_%=:\n\t"
        "mbarrier.try_wait.parity.acquire.cta.shared::cta.b64 P, [%0], %1, 0x989680;\n\t"
        "@P bra DONE_%=;\n\t"
        "bra WAIT_%=;\n\t"
        "DONE_%=:\n\t"
        "}" :: "r"(mbar), "r"(parity) : "memory");
}

// ---------------- fused prelude: quantize x + convert w, tile-major swizzled ------
__global__ void __launch_bounds__(256) prelude_kernel(const float* __restrict__ x,
                                                      const int* __restrict__ w,
                                                      const float* __restrict__ is_p,
                                                      const int* __restrict__ izp_p,
                                                      const int* __restrict__ wzp) {
    int b = blockIdx.x;
    if (b < 16384) {
        size_t base = ((size_t)b * 256 + threadIdx.x) * 8;
        float inv = 1.0f / is_p[0];
        float zp = (float)izp_p[0];
        float4 v0 = *(const float4*)(x + base);
        float4 v1 = *(const float4*)(x + base + 4);
        float q[8];
        q[0] = v0.x; q[1] = v0.y; q[2] = v0.z; q[3] = v0.w;
        q[4] = v1.x; q[5] = v1.y; q[6] = v1.z; q[7] = v1.w;
#pragma unroll
        for (int i = 0; i < 8; i++)
            q[i] = fminf(fmaxf(rintf(q[i] * inv) + zp, -128.f), 127.f) - zp;
        uint4 o;
        o.x = pack_bf16(q[0], q[1]);
        o.y = pack_bf16(q[2], q[3]);
        o.z = pack_bf16(q[4], q[5]);
        o.w = pack_bf16(q[6], q[7]);
        int m = (int)(base >> 12);
        int k = (int)(base & 4095);
        int mt = m >> 7, row = m & 127;
        int ks = k >> 6, u = (k & 63) >> 3;
        size_t dst = (size_t)(mt * 64 + ks) * A_TILE_BYTES +
                     row * 128 + ((u ^ (row & 7)) << 4);
        *reinterpret_cast<uint4*>(reinterpret_cast<char*>(g_xq) + dst) = o;
    } else {
        size_t base = ((size_t)(b - 16384) * 256 + threadIdx.x) * 8;
        int n = (int)(base >> 12);
        int k = (int)(base & 4095);
        int zp = wzp[n];
        int4 a = *(const int4*)(w + base);
        int4 c = *(const int4*)(w + base + 4);
        uint4 o;
        o.x = pack_bf16((float)(a.x - zp), (float)(a.y - zp));
        o.y = pack_bf16((float)(a.z - zp), (float)(a.w - zp));
        o.z = pack_bf16((float)(c.x - zp), (float)(c.y - zp));
        o.w = pack_bf16((float)(c.z - zp), (float)(c.w - zp));
        int nt = n >> 8, row = n & 255;
        int ks = k >> 6, u = (k & 63) >> 3;
        size_t dst = (size_t)(nt * 64 + ks) * B_TILE_BYTES +
                     row * 128 + ((u ^ (row & 7)) << 4);
        *reinterpret_cast<uint4*>(reinterpret_cast<char*>(g_wq) + dst) = o;
    }
}

// ---------------- persistent HMMA bf16 GEMM, warp-specialized producer ----------------
// smem: [0,16) full mbars, [16,32) empty mbars, stages @4096 (96KB each)
#define S_STAGE (A_STEP + B_STEP)               // 98304
#define S_BUF 4096
#define SMEM_BYTES (S_BUF + 2 * S_STAGE)        // 200704

__device__ __forceinline__ void tile_coords(int t, int& mt, int& nt) {
    int g = t >> 7;          // group of 8 m-tiles x 16 n-tiles
    int r = t & 127;
    mt = g * 8 + (r & 7);
    nt = r >> 3;
}

__global__ void __launch_bounds__(THREADS, 1)
gemm_kernel(const float* __restrict__ wscale, const float* __restrict__ in_scale,
            const int* __restrict__ bias_int, const float* __restrict__ bias_scale,
            float* __restrict__ out) {
    extern __shared__ __align__(1024) char smem[];
    const uint32_t sbase = smem_u32(smem);
    const int tid = threadIdx.x;
    const int lane = tid & 31;
    const int wid = tid >> 5;
    const int bid = blockIdx.x;

    const uint32_t FULL0 = sbase, FULL1 = sbase + 8;
    const uint32_t EMPTY0 = sbase + 16, EMPTY1 = sbase + 24;

    const char* xbase = reinterpret_cast<const char*>(g_xq);
    const char* wbase = reinterpret_cast<const char*>(g_wq);

    if (tid == 0) {
        MBAR_INIT(FULL0, 1);
        MBAR_INIT(FULL1, 1);
        MBAR_INIT(EMPTY0, NCOMPUTE_WARPS);
        MBAR_INIT(EMPTY1, NCOMPUTE_WARPS);
    }
    __syncthreads();

    if (wid == NCOMPUTE_WARPS) {
        // ---------------- producer warp: pure load pipeline ----------------
        if (lane == 0) {
            uint32_t p = 0;
            for (int t2 = bid; t2 < NTILES; t2 += GRIDX) {
                int mt2, nt2;
                tile_coords(t2, mt2, nt2);
                const char* bA = xbase + (size_t)mt2 * 64 * A_TILE_BYTES;
                const char* bB = wbase + (size_t)nt2 * 64 * B_TILE_BYTES;
#pragma unroll 1
                for (int it = 0; it < ITERS_PER_TILE; it++, p++) {
                    uint32_t s = p & 1;
                    uint32_t j = p >> 1;
                    if (j > 0) mbar_wait(s ? EMPTY1 : EMPTY0, (j - 1) & 1);
                    uint32_t fmb = s ? FULL1 : FULL0;
                    MBAR_EXPECT_TX(fmb, S_STAGE);
                    uint32_t dst = sbase + S_BUF + s * S_STAGE;
                    bulk_ld(dst, bA + (size_t)it * A_STEP, A_STEP, fmb);
                    bulk_ld(dst + A_STEP, bB + (size_t)it * B_STEP, B_STEP, fmb);
                }
            }
        }
        return;   // producer warp exits; outstanding bulk copies complete via mbars
    }

    // ---------------- compute warps 0..7 ----------------
    const int warpM = wid >> 2;       // 2 -> 64 rows each
    const int warpN = wid & 3;        // 4 -> 64 cols each
    const float is = in_scale[0];

    float acc[4][8][4];
#pragma unroll
    for (int i = 0; i < 4; i++)
#pragma unroll
        for (int j = 0; j < 8; j++)
#pragma unroll
            for (int q = 0; q < 4; q++) acc[i][j][q] = 0.0f;

    // ldmatrix lane-address components (swizzled rows of 128B)
    const int a_row = lane & 15;
    const int a_kh = (lane >> 4) & 1;
    const int b_noff = (lane & 7) + ((lane & 16) >> 1);
    const int b_kh = (lane >> 3) & 1;

    int rA[4], rB[4];
#pragma unroll
    for (int mi = 0; mi < 4; mi++) rA[mi] = warpM * 64 + mi * 16 + a_row;
#pragma unroll
    for (int np = 0; np < 4; np++) rB[np] = warpN * 64 + np * 16 + b_noff;

    int t = bid;
    int mt, nt;
    tile_coords(t, mt, nt);
    uint32_t git = 0;   // flat position counter

    while (true) {
#pragma unroll 1
        for (int it = 0; it < ITERS_PER_TILE; it++, git++) {
            uint32_t slot = git & 1;
            mbar_wait(slot ? FULL1 : FULL0, (git >> 1) & 1);

            uint32_t sA = sbase + S_BUF + slot * S_STAGE;
            uint32_t sB = sA + A_STEP;

#pragma unroll
            for (int ks = 0; ks < 8; ks++) {   // eight k=16 steps
                uint32_t a[4][4], b[4][4];
                uint32_t sAsub = sA + (ks >> 2) * A_TILE_BYTES;
                uint32_t sBsub = sB + (ks >> 2) * B_TILE_BYTES;
                int uA = (ks & 3) * 2 + a_kh;
                int uB = (ks & 3) * 2 + b_kh;
#pragma unroll
                for (int mi = 0; mi < 4; mi++)
                    ldm_x4(a[mi], sAsub + rA[mi] * 128 + ((uA ^ (rA[mi] & 7)) << 4));
#pragma unroll
                for (int np = 0; np < 4; np++)
                    ldm_x4(b[np], sBsub + rB[np] * 128 + ((uB ^ (rB[np] & 7)) << 4));
#pragma unroll
                for (int mi = 0; mi < 4; mi++)
#pragma unroll
                    for (int ni = 0; ni < 8; ni++)
                        mma_bf16(acc[mi][ni], a[mi], &b[ni >> 1][(ni & 1) * 2]);
            }

            if (lane == 0) MBAR_ARRIVE(slot ? EMPTY1 : EMPTY0);
        }

        // epilogue for tile t (next tile's loads already in flight via producer)
        {
            const int m0 = mt * TILE_M;
            const int n0 = nt * TILE_N;
            const int gid = lane >> 2, tig = lane & 3;
#pragma unroll
            for (int ni = 0; ni < 8; ni++) {
                int n = n0 + warpN * 64 + ni * 8 + tig * 2;
                float al0 = is * wscale[n];
                float al1 = is * wscale[n + 1];
                float be0 = (float)bias_int[n] * bias_scale[n];
                float be1 = (float)bias_int[n + 1] * bias_scale[n + 1];
#pragma unroll
                for (int mi = 0; mi < 4; mi++) {
                    size_t r = (size_t)m0 + warpM * 64 + mi * 16 + gid;
                    float2 v0 = {acc[mi][ni][0] * al0 + be0, acc[mi][ni][1] * al1 + be1};
                    float2 v1 = {acc[mi][ni][2] * al0 + be0, acc[mi][ni][3] * al1 + be1};
                    *reinterpret_cast<float2*>(out + r * NDIM + n) = v0;
                    *reinterpret_cast<float2*>(out + (r + 8) * NDIM + n) = v1;
                    acc[mi][ni][0] = 0.0f; acc[mi][ni][1] = 0.0f;
                    acc[mi][ni][2] = 0.0f; acc[mi][ni][3] = 0.0f;
                }
            }
        }

        t += GRIDX;
        if (t >= NTILES) break;
        tile_coords(t, mt, nt);
    }
}

// ---------------- launch ----------------
extern "C" void kernel_launch(void* const* d_in, const int* in_sizes, int n_in,
                              void* d_out, int out_size) {
    const float* x = (const float*)d_in[0];
    const int* w = (const int*)d_in[1];
    const float* wsc = (const float*)d_in[2];
    const int* wzp = (const int*)d_in[3];
    const float* isc = (const float*)d_in[4];
    const int* izp = (const int*)d_in[5];
    const int* bi = (const int*)d_in[6];
    const float* bsc = (const float*)d_in[7];
    float* out = (float*)d_out;

    cudaFuncSetAttribute(gemm_kernel, cudaFuncAttributeMaxDynamicSharedMemorySize,
                         SMEM_BYTES);

    prelude_kernel<<<16384 + 8192, 256>>>(x, w, isc, izp, wzp);
    gemm_kernel<<<GRIDX, THREADS, SMEM_BYTES>>>(wsc, isc, bi, bsc, out);
}

// round 14
// speedup vs baseline: 1.2024x; 1.0921x over previous
#include <cuda_runtime.h>
#include <cuda_bf16.h>
#include <cstdint>

#define MDIM 8192
#define KDIM 4096
#define NDIM 4096

#define TILE_M 128
#define TILE_N 256
#define ITERS_PER_TILE 32      // k-positions of 128 per tile
#define NTILES 1024            // 64 m-tiles x 16 n-tiles
#define GRIDX 148
#define THREADS 256
#define NWARPS (THREADS / 32)

// Tile-major pre-swizzled scratch:
// g_xq: [mt(64)][ks(64)] tiles of 128x64 bf16, rows 128B, XOR-swizzled
// g_wq: [nt(16)][ks(64)] tiles of 256x64 bf16
__device__ __nv_bfloat16 g_xq[(size_t)MDIM * KDIM];
__device__ __nv_bfloat16 g_wq[(size_t)NDIM * KDIM];

#define A_TILE_BYTES 16384
#define B_TILE_BYTES 32768
#define A_STEP (2 * A_TILE_BYTES)   // 32768 per position
#define B_STEP (2 * B_TILE_BYTES)   // 65536 per position

// ---------------- helpers ----------------
__device__ __forceinline__ uint32_t smem_u32(const void* p) {
    uint32_t a;
    asm("{ .reg .u64 t; cvta.to.shared.u64 t, %1; cvt.u32.u64 %0, t; }" : "=r"(a) : "l"(p));
    return a;
}
__device__ __forceinline__ void ldm_x4(uint32_t* r, uint32_t addr) {
    asm volatile("ldmatrix.sync.aligned.m8n8.x4.shared.b16 {%0,%1,%2,%3}, [%4];"
                 : "=r"(r[0]), "=r"(r[1]), "=r"(r[2]), "=r"(r[3]) : "r"(addr));
}
__device__ __forceinline__ void mma_bf16(float* d, const uint32_t* a, const uint32_t* b) {
    asm volatile(
        "mma.sync.aligned.m16n8k16.row.col.f32.bf16.bf16.f32 "
        "{%0,%1,%2,%3}, {%4,%5,%6,%7}, {%8,%9}, {%0,%1,%2,%3};"
        : "+f"(d[0]), "+f"(d[1]), "+f"(d[2]), "+f"(d[3])
        : "r"(a[0]), "r"(a[1]), "r"(a[2]), "r"(a[3]), "r"(b[0]), "r"(b[1]));
}
__device__ __forceinline__ uint32_t pack_bf16(float a, float b) {
    __nv_bfloat162 t = __floats2bfloat162_rn(a, b);
    return *reinterpret_cast<uint32_t*>(&t);
}
__device__ __forceinline__ void bulk_ld(uint32_t dst, const void* src, uint32_t bytes,
                                        uint32_t mbar) {
    asm volatile(
        "cp.async.bulk.shared::cta.global.mbarrier::complete_tx::bytes [%0], [%1], %2, [%3];"
        :: "r"(dst), "l"(src), "r"(bytes), "r"(mbar) : "memory");
}
#define MBAR_INIT(addr, cnt) \
    asm volatile("mbarrier.init.shared.b64 [%0], %1;" :: "r"(addr), "r"(cnt) : "memory")
#define MBAR_EXPECT_TX(addr, bytes) \
    asm volatile("mbarrier.arrive.expect_tx.shared.b64 _, [%0], %1;" \
                 :: "r"(addr), "r"(bytes) : "memory")
#define MBAR_ARRIVE(addr) \
    asm volatile("mbarrier.arrive.release.cta.shared.b64 _, [%0];" :: "r"(addr) : "memory")
__device__ __forceinline__ void mbar_wait(uint32_t mbar, uint32_t parity) {
    asm volatile(
        "{\n\t"
        ".reg .pred P;\n\t"
        "WAIT_%=:\n\t"
        "mbarrier.try_wait.parity.acquire.cta.shared::cta.b64 P, [%0], %1, 0x989680;\n\t"
        "@P bra DONE_%=;\n\t"
        "bra WAIT_%=;\n\t"
        "DONE_%=:\n\t"
        "}" :: "r"(mbar), "r"(parity) : "memory");
}

// ---------------- fused prelude: quantize x + convert w, tile-major swizzled ------
__global__ void __launch_bounds__(256) prelude_kernel(const float* __restrict__ x,
                                                      const int* __restrict__ w,
                                                      const float* __restrict__ is_p,
                                                      const int* __restrict__ izp_p,
                                                      const int* __restrict__ wzp) {
    int b = blockIdx.x;
    if (b < 16384) {
        size_t base = ((size_t)b * 256 + threadIdx.x) * 8;
        float inv = 1.0f / is_p[0];
        float zp = (float)izp_p[0];
        float4 v0 = *(const float4*)(x + base);
        float4 v1 = *(const float4*)(x + base + 4);
        float q[8];
        q[0] = v0.x; q[1] = v0.y; q[2] = v0.z; q[3] = v0.w;
        q[4] = v1.x; q[5] = v1.y; q[6] = v1.z; q[7] = v1.w;
#pragma unroll
        for (int i = 0; i < 8; i++)
            q[i] = fminf(fmaxf(rintf(q[i] * inv) + zp, -128.f), 127.f) - zp;
        uint4 o;
        o.x = pack_bf16(q[0], q[1]);
        o.y = pack_bf16(q[2], q[3]);
        o.z = pack_bf16(q[4], q[5]);
        o.w = pack_bf16(q[6], q[7]);
        int m = (int)(base >> 12);
        int k = (int)(base & 4095);
        int mt = m >> 7, row = m & 127;
        int ks = k >> 6, u = (k & 63) >> 3;
        size_t dst = (size_t)(mt * 64 + ks) * A_TILE_BYTES +
                     row * 128 + ((u ^ (row & 7)) << 4);
        *reinterpret_cast<uint4*>(reinterpret_cast<char*>(g_xq) + dst) = o;
    } else {
        size_t base = ((size_t)(b - 16384) * 256 + threadIdx.x) * 8;
        int n = (int)(base >> 12);
        int k = (int)(base & 4095);
        int zp = wzp[n];
        int4 a = *(const int4*)(w + base);
        int4 c = *(const int4*)(w + base + 4);
        uint4 o;
        o.x = pack_bf16((float)(a.x - zp), (float)(a.y - zp));
        o.y = pack_bf16((float)(a.z - zp), (float)(a.w - zp));
        o.z = pack_bf16((float)(c.x - zp), (float)(c.y - zp));
        o.w = pack_bf16((float)(c.z - zp), (float)(c.w - zp));
        int nt = n >> 8, row = n & 255;
        int ks = k >> 6, u = (k & 63) >> 3;
        size_t dst = (size_t)(nt * 64 + ks) * B_TILE_BYTES +
                     row * 128 + ((u ^ (row & 7)) << 4);
        *reinterpret_cast<uint4*>(reinterpret_cast<char*>(g_wq) + dst) = o;
    }
}

// ---------------- persistent HMMA bf16 GEMM, fragment double-buffered ----------------
// smem: [0,16) full mbars, [16,32) empty mbars, stages @4096 (96KB each)
#define S_STAGE (A_STEP + B_STEP)               // 98304
#define S_BUF 4096
#define SMEM_BYTES (S_BUF + 2 * S_STAGE)        // 200704

__device__ __forceinline__ void tile_coords(int t, int& mt, int& nt) {
    int g = t >> 7;          // group of 8 m-tiles x 16 n-tiles
    int r = t & 127;
    mt = g * 8 + (r & 7);
    nt = r >> 3;
}

__device__ __forceinline__ void load_frag(uint32_t sA, uint32_t sB, int ks,
                                          int a_kh, int b_kh,
                                          const int* rA, const int* rB,
                                          uint32_t (*A)[4], uint32_t (*B)[4]) {
    uint32_t sAs = sA + (ks >> 2) * A_TILE_BYTES;
    uint32_t sBs = sB + (ks >> 2) * B_TILE_BYTES;
    int uA = (ks & 3) * 2 + a_kh;
    int uB = (ks & 3) * 2 + b_kh;
#pragma unroll
    for (int mi = 0; mi < 4; mi++)
        ldm_x4(A[mi], sAs + rA[mi] * 128 + ((uA ^ (rA[mi] & 7)) << 4));
#pragma unroll
    for (int np = 0; np < 4; np++)
        ldm_x4(B[np], sBs + rB[np] * 128 + ((uB ^ (rB[np] & 7)) << 4));
}

__device__ __forceinline__ void mma_frag(float (*acc)[8][4],
                                         uint32_t (*A)[4], uint32_t (*B)[4]) {
#pragma unroll
    for (int mi = 0; mi < 4; mi++)
#pragma unroll
        for (int ni = 0; ni < 8; ni++)
            mma_bf16(acc[mi][ni], A[mi], &B[ni >> 1][(ni & 1) * 2]);
}

__global__ void __launch_bounds__(THREADS, 1)
gemm_kernel(const float* __restrict__ wscale, const float* __restrict__ in_scale,
            const int* __restrict__ bias_int, const float* __restrict__ bias_scale,
            float* __restrict__ out) {
    extern __shared__ __align__(1024) char smem[];
    const uint32_t sbase = smem_u32(smem);
    const int tid = threadIdx.x;
    const int lane = tid & 31;
    const int wid = tid >> 5;
    const int warpM = wid >> 2;       // 2 -> 64 rows each
    const int warpN = wid & 3;        // 4 -> 64 cols each
    const int bid = blockIdx.x;

    const uint32_t FULL0 = sbase, FULL1 = sbase + 8;
    const uint32_t EMPTY0 = sbase + 16, EMPTY1 = sbase + 24;

    const char* xbase = reinterpret_cast<const char*>(g_xq);
    const char* wbase = reinterpret_cast<const char*>(g_wq);

    if (tid == 0) {
        MBAR_INIT(FULL0, 1);
        MBAR_INIT(FULL1, 1);
        MBAR_INIT(EMPTY0, NWARPS);
        MBAR_INIT(EMPTY1, NWARPS);
    }
    __syncthreads();

    const float is = in_scale[0];

    int t = bid;
    int mt, nt;
    tile_coords(t, mt, nt);

    // prologue: flat position 0 in flight
    if (tid == 0) {
        MBAR_EXPECT_TX(FULL0, S_STAGE);
        bulk_ld(sbase + S_BUF, xbase + (size_t)mt * 64 * A_TILE_BYTES, A_STEP, FULL0);
        bulk_ld(sbase + S_BUF + A_STEP, wbase + (size_t)nt * 64 * B_TILE_BYTES,
                B_STEP, FULL0);
    }

    float acc[4][8][4];
#pragma unroll
    for (int i = 0; i < 4; i++)
#pragma unroll
        for (int j = 0; j < 8; j++)
#pragma unroll
            for (int q = 0; q < 4; q++) acc[i][j][q] = 0.0f;

    // ldmatrix lane-address components (swizzled rows of 128B)
    const int a_row = lane & 15;
    const int a_kh = (lane >> 4) & 1;
    const int b_noff = (lane & 7) + ((lane & 16) >> 1);
    const int b_kh = (lane >> 3) & 1;

    int rA[4], rB[4];
#pragma unroll
    for (int mi = 0; mi < 4; mi++) rA[mi] = warpM * 64 + mi * 16 + a_row;
#pragma unroll
    for (int np = 0; np < 4; np++) rB[np] = warpN * 64 + np * 16 + b_noff;

    uint32_t git = 0;   // flat position counter (pipeline phase source)

    while (true) {
#pragma unroll 1
        for (int it = 0; it < ITERS_PER_TILE; it++, git++) {
            // producer: issue load for flat position git+1
            if (tid == 0) {
                int nit = it + 1;
                int t2 = t;
                if (nit == ITERS_PER_TILE) { nit = 0; t2 = t + GRIDX; }
                if (t2 < NTILES) {
                    int mt2, nt2;
                    tile_coords(t2, mt2, nt2);
                    uint32_t pgit = git + 1;
                    uint32_t s = pgit & 1;
                    uint32_t j = pgit >> 1;
                    if (j > 0) mbar_wait(s ? EMPTY1 : EMPTY0, (j - 1) & 1);
                    uint32_t fmb = s ? FULL1 : FULL0;
                    MBAR_EXPECT_TX(fmb, S_STAGE);
                    uint32_t dst = sbase + S_BUF + s * S_STAGE;
                    bulk_ld(dst, xbase + (size_t)(mt2 * 64 + nit * 2) * A_TILE_BYTES,
                            A_STEP, fmb);
                    bulk_ld(dst + A_STEP,
                            wbase + (size_t)(nt2 * 64 + nit * 2) * B_TILE_BYTES,
                            B_STEP, fmb);
                }
            }

            uint32_t slot = git & 1;
            mbar_wait(slot ? FULL1 : FULL0, (git >> 1) & 1);

            uint32_t sA = sbase + S_BUF + slot * S_STAGE;
            uint32_t sB = sA + A_STEP;

            // software-pipelined fragment double-buffer over 8 k=16 steps
            uint32_t a0[4][4], b0[4][4], a1[4][4], b1[4][4];
            load_frag(sA, sB, 0, a_kh, b_kh, rA, rB, a0, b0);
#pragma unroll
            for (int p = 0; p < 4; p++) {
                load_frag(sA, sB, 2 * p + 1, a_kh, b_kh, rA, rB, a1, b1);
                mma_frag(acc, a0, b0);
                if (p < 3)
                    load_frag(sA, sB, 2 * p + 2, a_kh, b_kh, rA, rB, a0, b0);
                mma_frag(acc, a1, b1);
            }

            if (lane == 0) MBAR_ARRIVE(slot ? EMPTY1 : EMPTY0);
        }

        // epilogue for tile t (next tile's stage-0 load already in flight)
        {
            const int m0 = mt * TILE_M;
            const int n0 = nt * TILE_N;
            const int gid = lane >> 2, tig = lane & 3;
#pragma unroll
            for (int ni = 0; ni < 8; ni++) {
                int n = n0 + warpN * 64 + ni * 8 + tig * 2;
                float al0 = is * wscale[n];
                float al1 = is * wscale[n + 1];
                float be0 = (float)bias_int[n] * bias_scale[n];
                float be1 = (float)bias_int[n + 1] * bias_scale[n + 1];
#pragma unroll
                for (int mi = 0; mi < 4; mi++) {
                    size_t r = (size_t)m0 + warpM * 64 + mi * 16 + gid;
                    float2 v0 = {acc[mi][ni][0] * al0 + be0, acc[mi][ni][1] * al1 + be1};
                    float2 v1 = {acc[mi][ni][2] * al0 + be0, acc[mi][ni][3] * al1 + be1};
                    *reinterpret_cast<float2*>(out + r * NDIM + n) = v0;
                    *reinterpret_cast<float2*>(out + (r + 8) * NDIM + n) = v1;
                    acc[mi][ni][0] = 0.0f; acc[mi][ni][1] = 0.0f;
                    acc[mi][ni][2] = 0.0f; acc[mi][ni][3] = 0.0f;
                }
            }
        }

        t += GRIDX;
        if (t >= NTILES) break;
        tile_coords(t, mt, nt);
    }
}

// ---------------- launch ----------------
extern "C" void kernel_launch(void* const* d_in, const int* in_sizes, int n_in,
                              void* d_out, int out_size) {
    const float* x = (const float*)d_in[0];
    const int* w = (const int*)d_in[1];
    const float* wsc = (const float*)d_in[2];
    const int* wzp = (const int*)d_in[3];
    const float* isc = (const float*)d_in[4];
    const int* izp = (const int*)d_in[5];
    const int* bi = (const int*)d_in[6];
    const float* bsc = (const float*)d_in[7];
    float* out = (float*)d_out;

    cudaFuncSetAttribute(gemm_kernel, cudaFuncAttributeMaxDynamicSharedMemorySize,
                         SMEM_BYTES);

    prelude_kernel<<<16384 + 8192, 256>>>(x, w, isc, izp, wzp);
    gemm_kernel<<<GRIDX, THREADS, SMEM_BYTES>>>(wsc, isc, bi, bsc, out);
}